// round 14
// baseline (speedup 1.0000x reference)
#include <cuda_runtime.h>
#include <cuda_bf16.h>
#include <cuda_fp16.h>
#include <cstdint>
#include <math.h>

#define NN   50000
#define EE   300000
#define FIN  16
#define FE   8
#define HH   64
#define HEADS 4
#define NGRP 64
#define KK   1024
#define E2   (EE + NN)
#define NPART 512
#define CHUNKS 16
#define CK   64               // k per chunk
#define NPB  3125             // nodes per Q batch
#define NB   16               // batches

// ---------------- scratch ----------------
// Q ping-pong: [NPB][k/2][hp][2] fp16-pair interleave, 409 MB each
static __device__ __half g_QA[(size_t)NPB * KK * HH];
static __device__ __half g_QB[(size_t)NPB * KK * HH];

static __device__ int   g_cnt[NN];
static __device__ int   g_ptr[NN + 1];
static __device__ int   g_cursor[NN];
static __device__ int   g_eperm[EE];
static __device__ int   g_deg[NN];
static __device__ int   g_ptr2[NN + 1];     // dst CSR
static __device__ int   g_cursor2[NN];
static __device__ int   g_eperm2[EE];
static __device__ float g_agg[NN * HH];
static __device__ float g_h[NN * HH];
static __device__ float g_xh[NN * HH];
static __device__ float g_asrc[NN * HEADS];
static __device__ float g_adst[NN * HEADS];
static __device__ float g_h2[NN * HH];
static __device__ float g_pool[NGRP * HH];
static __device__ int   g_gcnt[NGRP];
static __device__ float g_psum[NPART];
static __device__ float g_psumsq[NPART];
static __device__ float g_stats[4];

__device__ __forceinline__ void cp16(uint32_t dst_s, const void* src_g) {
    asm volatile("cp.async.cg.shared.global [%0], [%1], 16;\n"
                 :: "r"(dst_s), "l"(src_g));
}

// ---------------- CSR by src AND dst ----------------
__global__ void k_hist(const int* __restrict__ ei) {
    int e = blockIdx.x * blockDim.x + threadIdx.x;
    if (e >= EE) return;
    atomicAdd(&g_cnt[ei[e]], 1);
    atomicAdd(&g_deg[ei[EE + e]], 1);
}

__global__ void k_scan() {
    __shared__ int ss[1024];
    const int CH = (NN + 1023) / 1024;
    int t = threadIdx.x;
    int lo = t * CH;
    int hi = lo + CH; if (hi > NN) hi = NN;
    int s = 0;
    for (int i = lo; i < hi; i++) s += g_cnt[i];
    ss[t] = s;
    __syncthreads();
    for (int off = 1; off < 1024; off <<= 1) {
        int v = (t >= off) ? ss[t - off] : 0;
        __syncthreads();
        ss[t] += v;
        __syncthreads();
    }
    int run = ss[t] - s;
    for (int i = lo; i < hi; i++) {
        g_ptr[i] = run;
        g_cursor[i] = run;
        run += g_cnt[i];
    }
    if (t == 0) g_ptr[NN] = EE;
    __syncthreads();
    s = 0;
    for (int i = lo; i < hi; i++) s += g_deg[i];
    ss[t] = s;
    __syncthreads();
    for (int off = 1; off < 1024; off <<= 1) {
        int v = (t >= off) ? ss[t - off] : 0;
        __syncthreads();
        ss[t] += v;
        __syncthreads();
    }
    run = ss[t] - s;
    for (int i = lo; i < hi; i++) {
        g_ptr2[i] = run;
        g_cursor2[i] = run;
        run += g_deg[i];
    }
    if (t == 0) g_ptr2[NN] = EE;
}

__global__ void k_scatter(const int* __restrict__ ei) {
    int e = blockIdx.x * blockDim.x + threadIdx.x;
    if (e >= EE) return;
    int pos = atomicAdd(&g_cursor[ei[e]], 1);
    g_eperm[pos] = e;
    int pos2 = atomicAdd(&g_cursor2[ei[EE + e]], 1);
    g_eperm2[pos2] = e;
}

// ---- Q[nl][kp][hp][2] = sum_f x[n0+nl,f] * W2[k, f*64+h]  (fp16 batch) ----
// block: 256 thr = 8 k-rows x 32 h-pairs; each thread does 4 k-rows
// (kg, +256, +512, +768) sharing the x LDS loads.
__global__ void __launch_bounds__(256)
k_Q(const float* __restrict__ x, const float* __restrict__ w2, int n0, int which) {
    __half2* q = (__half2*)(which ? g_QB : g_QA);
    int kl = threadIdx.x >> 5;
    int hp = threadIdx.x & 31;
    int kg0 = blockIdx.y * 8 + kl;       // 0..255
    int nl0 = blockIdx.x * 32;

    __shared__ float2 xs2[32 * 16];
    for (int i = threadIdx.x; i < 512; i += 256) {
        int nl = i >> 4, f = i & 15;
        int n = n0 + nl0 + nl;
        float v = (n < NN) ? x[n * 16 + f] : 0.f;
        xs2[i] = make_float2(v, v);
    }

    unsigned long long w0[16], w1r[16], w2r[16], w3[16];
#pragma unroll
    for (int f = 0; f < 16; f++) {
        w0[f]  = *(const unsigned long long*)(w2 + (size_t)(kg0)       * 1024 + f * 64 + hp * 2);
        w1r[f] = *(const unsigned long long*)(w2 + (size_t)(kg0 + 256) * 1024 + f * 64 + hp * 2);
        w2r[f] = *(const unsigned long long*)(w2 + (size_t)(kg0 + 512) * 1024 + f * 64 + hp * 2);
        w3[f]  = *(const unsigned long long*)(w2 + (size_t)(kg0 + 768) * 1024 + f * 64 + hp * 2);
    }
    __syncthreads();

    // pair-interleave: idx = n*32768 + (k>>1)*64 + hp*2 + (k&1)
    int par = kg0 & 1;
    size_t off0 = (size_t)((kg0)       >> 1) * 64 + (hp << 1) + par;
    size_t off1 = (size_t)((kg0 + 256) >> 1) * 64 + (hp << 1) + par;
    size_t off2 = (size_t)((kg0 + 512) >> 1) * 64 + (hp << 1) + par;
    size_t off3 = (size_t)((kg0 + 768) >> 1) * 64 + (hp << 1) + par;

#pragma unroll 2
    for (int nl = 0; nl < 32; nl++) {
        if (nl0 + nl >= NPB) break;
        unsigned long long a0 = 0ULL, a1 = 0ULL, a2 = 0ULL, a3 = 0ULL;
        const unsigned long long* xp = (const unsigned long long*)(xs2 + nl * 16);
#pragma unroll
        for (int f = 0; f < 16; f++) {
            unsigned long long xv = xp[f];
            asm("fma.rn.f32x2 %0, %1, %2, %0;" : "+l"(a0) : "l"(xv), "l"(w0[f]));
            asm("fma.rn.f32x2 %0, %1, %2, %0;" : "+l"(a1) : "l"(xv), "l"(w1r[f]));
            asm("fma.rn.f32x2 %0, %1, %2, %0;" : "+l"(a2) : "l"(xv), "l"(w2r[f]));
            asm("fma.rn.f32x2 %0, %1, %2, %0;" : "+l"(a3) : "l"(xv), "l"(w3[f]));
        }
        float l0, h0, l1, h1, l2, h2, l3, h3;
        asm("mov.b64 {%0,%1}, %2;" : "=f"(l0), "=f"(h0) : "l"(a0));
        asm("mov.b64 {%0,%1}, %2;" : "=f"(l1), "=f"(h1) : "l"(a1));
        asm("mov.b64 {%0,%1}, %2;" : "=f"(l2), "=f"(h2) : "l"(a2));
        asm("mov.b64 {%0,%1}, %2;" : "=f"(l3), "=f"(h3) : "l"(a3));
        size_t nb = (size_t)(nl0 + nl) * 32768;
        q[nb + off0] = __floats2half2_rn(l0, h0);
        q[nb + off1] = __floats2half2_rn(l1, h1);
        q[nb + off2] = __floats2half2_rn(l2, h2);
        q[nb + off3] = __floats2half2_rn(l3, h3);
    }
}

// ---- per-edge message: msg = r_e @ Q_src + x_src@b2'  (R11 scalar dot) ----
__global__ void k_msg(const float* __restrict__ x, const float* __restrict__ ea,
                      const int* __restrict__ ei, const float* __restrict__ w1,
                      const float* __restrict__ b1, const float* __restrict__ b2,
                      int n0, int which) {
    const __half* qb0 = which ? g_QB : g_QA;
    int nl = blockIdx.x;
    int n = n0 + nl;
    int p0 = g_ptr[n], p1 = g_ptr[n + 1];
    if (p0 == p1) return;

    __shared__ __align__(16) uint2 qbuf[2][(CK / 2) * 32];   // 2 x 8KB
    __shared__ __align__(8) float r_s[8][2][CK];
    __shared__ float bx[64];

    int tid = threadIdx.x;
    int wid = tid >> 5, lane = tid & 31;

    if (tid < 64) {
        float s = 0.f;
        const float* xv = x + n * 16;
#pragma unroll
        for (int f = 0; f < 16; f++) s = fmaf(xv[f], b2[f * 64 + tid], s);
        bx[tid] = s;
    }

    const char* qg = (const char*)qb0 + (size_t)nl * (KK * HH * 2);
    uint32_t sbase = (uint32_t)__cvta_generic_to_shared(&qbuf[0][0]);
    uint32_t soff = tid * 16;

    for (int ebase = p0; ebase < p1; ebase += 16) {
        int t0 = ebase + wid, t1 = ebase + 8 + wid;
        bool e0v = t0 < p1, e1v = t1 < p1;
        int dst0 = 0, dst1 = 0;
        float ev0[8], ev1[8];
        if (e0v) {
            int e = g_eperm[t0];
            dst0 = ei[EE + e];
            const float4* p = (const float4*)(ea + (size_t)e * 8);
            float4 u = p[0], v = p[1];
            ev0[0]=u.x; ev0[1]=u.y; ev0[2]=u.z; ev0[3]=u.w;
            ev0[4]=v.x; ev0[5]=v.y; ev0[6]=v.z; ev0[7]=v.w;
        }
        if (e1v) {
            int e = g_eperm[t1];
            dst1 = ei[EE + e];
            const float4* p = (const float4*)(ea + (size_t)e * 8);
            float4 u = p[0], v = p[1];
            ev1[0]=u.x; ev1[1]=u.y; ev1[2]=u.z; ev1[3]=u.w;
            ev1[4]=v.x; ev1[5]=v.y; ev1[6]=v.z; ev1[7]=v.w;
        }
        float a00 = 0.f, a01 = 0.f, a10 = 0.f, a11 = 0.f;

        {
            uint32_t d = sbase + soff;
            const char* s = qg + soff;
            cp16(d, s); cp16(d + 4096, s + 4096);
            asm volatile("cp.async.commit_group;");
        }

        for (int c = 0; c < CHUNKS; c++) {
            if (c + 1 < CHUNKS) {
                uint32_t d = sbase + ((c + 1) & 1) * 8192 + soff;
                const char* s = qg + (c + 1) * 8192 + soff;
                cp16(d, s); cp16(d + 4096, s + 4096);
                asm volatile("cp.async.commit_group;");
                asm volatile("cp.async.wait_group 1;");
            } else {
                asm volatile("cp.async.wait_group 0;");
            }
            __syncthreads();

            if (e0v) {
#pragma unroll
                for (int j = 0; j < 2; j++) {
                    int k = c * 64 + j * 32 + lane;
                    float a = b1[k];
#pragma unroll
                    for (int f = 0; f < 8; f++) a = fmaf(ev0[f], w1[f * 1024 + k], a);
                    r_s[wid][0][j * 32 + lane] = fmaxf(a, 0.f);
                }
            }
            if (e1v) {
#pragma unroll
                for (int j = 0; j < 2; j++) {
                    int k = c * 64 + j * 32 + lane;
                    float a = b1[k];
#pragma unroll
                    for (int f = 0; f < 8; f++) a = fmaf(ev1[f], w1[f * 1024 + k], a);
                    r_s[wid][1][j * 32 + lane] = fmaxf(a, 0.f);
                }
            }
            __syncwarp();

            const uint2* qc = qbuf[c & 1];
            const float2* rr0 = (const float2*)r_s[wid][0];
            const float2* rr1 = (const float2*)r_s[wid][1];
            if (e0v) {
#pragma unroll 8
                for (int kp = 0; kp < CK / 2; kp++) {
                    uint2 v = qc[kp * 32 + lane];
                    float2 qa = __half22float2(*(const __half2*)&v.x);
                    float2 qb = __half22float2(*(const __half2*)&v.y);
                    float2 r0 = rr0[kp];
                    a00 = fmaf(r0.x, qa.x, a00);
                    a01 = fmaf(r0.x, qa.y, a01);
                    a00 = fmaf(r0.y, qb.x, a00);
                    a01 = fmaf(r0.y, qb.y, a01);
                    if (e1v) {
                        float2 r1 = rr1[kp];
                        a10 = fmaf(r1.x, qa.x, a10);
                        a11 = fmaf(r1.x, qa.y, a11);
                        a10 = fmaf(r1.y, qb.x, a10);
                        a11 = fmaf(r1.y, qb.y, a11);
                    }
                }
            }
            __syncthreads();
        }

        int h0 = lane * 2;
        if (e0v) {
            atomicAdd(&g_agg[(size_t)dst0 * 64 + h0],     a00 + bx[h0]);
            atomicAdd(&g_agg[(size_t)dst0 * 64 + h0 + 1], a01 + bx[h0 + 1]);
        }
        if (e1v) {
            atomicAdd(&g_agg[(size_t)dst1 * 64 + h0],     a10 + bx[h0]);
            atomicAdd(&g_agg[(size_t)dst1 * 64 + h0 + 1], a11 + bx[h0 + 1]);
        }
    }
}

// ---------------- NNConv epilogue ----------------
__global__ void k_conv(const float* __restrict__ x, const float* __restrict__ rw,
                       const float* __restrict__ cb) {
    int i = blockIdx.x * blockDim.x + threadIdx.x;
    if (i >= NN * HH) return;
    int n = i >> 6, j = i & 63;
    float d = fmaxf((float)g_deg[n], 1.f);
    float v = cb[j] + g_agg[i] / d;
    const float* xv = x + n * 16;
#pragma unroll
    for (int f = 0; f < 16; f++) v = fmaf(xv[f], rw[f * 64 + j], v);
    g_h[i] = fmaxf(v, 0.f);
}

// ---------------- graph layernorm reductions ----------------
__global__ void k_redpart(int which) {
    const float* src = which ? g_h2 : g_h;
    float s = 0.f, q = 0.f;
    for (int i = blockIdx.x * blockDim.x + threadIdx.x; i < NN * HH;
         i += NPART * 256) {
        float v = src[i];
        s += v; q = fmaf(v, v, q);
    }
    __shared__ float bs[256], bq[256];
    bs[threadIdx.x] = s; bq[threadIdx.x] = q;
    __syncthreads();
    for (int off = 128; off; off >>= 1) {
        if (threadIdx.x < off) {
            bs[threadIdx.x] += bs[threadIdx.x + off];
            bq[threadIdx.x] += bq[threadIdx.x + off];
        }
        __syncthreads();
    }
    if (threadIdx.x == 0) { g_psum[blockIdx.x] = bs[0]; g_psumsq[blockIdx.x] = bq[0]; }
}

__global__ void k_redfin(int which) {
    __shared__ double ds[NPART], dq[NPART];
    int t = threadIdx.x;
    ds[t] = (double)g_psum[t];
    dq[t] = (double)g_psumsq[t];
    __syncthreads();
    for (int off = NPART / 2; off; off >>= 1) {
        if (t < off) { ds[t] += ds[t + off]; dq[t] += dq[t + off]; }
        __syncthreads();
    }
    if (t == 0) {
        double M = (double)NN * HH;
        double mu = ds[0] / M;
        double var = dq[0] / M - mu * mu;
        if (var < 0.0) var = 0.0;
        float inv = 1.f / ((float)sqrt(var) + 1e-5f);
        g_stats[2 * which]     = (float)mu;
        g_stats[2 * which + 1] = inv;
    }
}

// ---------------- GAT ----------------
__global__ void k_gatprep(const float* __restrict__ gw, const float* __restrict__ asv,
                          const float* __restrict__ adv, const float* __restrict__ n1w,
                          const float* __restrict__ n1b) {
    int n = blockIdx.x, t = threadIdx.x;
    __shared__ float hs[64];
    float mu = g_stats[0], inv = g_stats[1];
    hs[t] = (g_h[(size_t)n * 64 + t] - mu) * inv * n1w[t] + n1b[t];
    __syncthreads();
    float v = 0.f;
#pragma unroll
    for (int i = 0; i < 64; i++) v = fmaf(hs[i], gw[i * 64 + t], v);
    g_xh[(size_t)n * 64 + t] = v;
    int hd = t >> 4, dd = t & 15;
    float ps = v * asv[t];
    float pd = v * adv[t];
#pragma unroll
    for (int off = 8; off; off >>= 1) {
        ps += __shfl_down_sync(0xffffffffu, ps, off, 16);
        pd += __shfl_down_sync(0xffffffffu, pd, off, 16);
    }
    if (dd == 0) {
        g_asrc[n * 4 + hd] = ps;
        g_adst[n * 4 + hd] = pd;
    }
}

__global__ void k_gatfused(const int* __restrict__ ei, const float* __restrict__ gb) {
    int n = blockIdx.x, t = threadIdx.x;
    int hd = t >> 4;
    int p0 = g_ptr2[n], p1 = g_ptr2[n + 1];
    float adst_n = g_adst[n * 4 + hd];

    float a_self = g_asrc[n * 4 + hd] + adst_n;
    a_self = (a_self > 0.f) ? a_self : 0.2f * a_self;
    float amax = a_self;
    for (int p = p0; p < p1; p++) {
        int s = ei[g_eperm2[p]];
        float a = g_asrc[s * 4 + hd] + adst_n;
        a = (a > 0.f) ? a : 0.2f * a;
        amax = fmaxf(amax, a);
    }
    float w = expf(a_self - amax);
    float sum = w;
    float acc = w * g_xh[(size_t)n * 64 + t];
    for (int p = p0; p < p1; p++) {
        int s = ei[g_eperm2[p]];
        float a = g_asrc[s * 4 + hd] + adst_n;
        a = (a > 0.f) ? a : 0.2f * a;
        float ww = expf(a - amax);
        sum += ww;
        acc = fmaf(ww, g_xh[(size_t)s * 64 + t], acc);
    }
    g_h2[(size_t)n * 64 + t] = fmaxf(acc / (sum + 1e-16f) + gb[t], 0.f);
}

__global__ void k_pool(const int* __restrict__ batch, const float* __restrict__ n2w,
                       const float* __restrict__ n2b) {
    int i = blockIdx.x * blockDim.x + threadIdx.x;
    if (i >= NN * HH) return;
    int n = i >> 6, j = i & 63;
    float v = (g_h2[i] - g_stats[2]) * g_stats[3] * n2w[j] + n2b[j];
    int g = batch[n];
    atomicAdd(&g_pool[g * 64 + j], v);
    if (j == 0) atomicAdd(&g_gcnt[g], 1);
}

__global__ void k_head(const float* __restrict__ lw, const float* __restrict__ lb,
                       float* __restrict__ out) {
    int g = blockIdx.x, t = threadIdx.x;
    float c = fmaxf((float)g_gcnt[g], 1.f);
    float v = (g_pool[g * 64 + t] / c) * lw[t];
    __shared__ float sm[64];
    sm[t] = v;
    __syncthreads();
    for (int off = 32; off; off >>= 1) {
        if (t < off) sm[t] += sm[t + off];
        __syncthreads();
    }
    if (t == 0) out[g] = sm[0] + lb[0];
}

// ---------------- launch ----------------
extern "C" void kernel_launch(void* const* d_in, const int* in_sizes, int n_in,
                              void* d_out, int out_size) {
    const float* x    = (const float*)d_in[0];
    const int*   ei   = (const int*)d_in[1];
    const float* ea   = (const float*)d_in[2];
    const int*   batch= (const int*)d_in[3];
    const float* enw1 = (const float*)d_in[4];
    const float* enb1 = (const float*)d_in[5];
    const float* enw2 = (const float*)d_in[6];
    const float* enb2 = (const float*)d_in[7];
    const float* rootw= (const float*)d_in[8];
    const float* convb= (const float*)d_in[9];
    const float* n1w  = (const float*)d_in[10];
    const float* n1b  = (const float*)d_in[11];
    const float* gatw = (const float*)d_in[12];
    const float* attS = (const float*)d_in[13];
    const float* attD = (const float*)d_in[14];
    const float* gatb = (const float*)d_in[15];
    const float* n2w  = (const float*)d_in[16];
    const float* n2b  = (const float*)d_in[17];
    const float* linw = (const float*)d_in[18];
    const float* linb = (const float*)d_in[19];
    float* out = (float*)d_out;

    static void *p_agg = 0, *p_cnt = 0, *p_deg = 0, *p_pool = 0, *p_gcnt = 0;
    static cudaStream_t s2;
    static cudaEvent_t ev_begin, evq[NB], evm[NB];
    static int init_done = 0;
    if (!init_done) {
        cudaGetSymbolAddress(&p_agg,  g_agg);
        cudaGetSymbolAddress(&p_cnt,  g_cnt);
        cudaGetSymbolAddress(&p_deg,  g_deg);
        cudaGetSymbolAddress(&p_pool, g_pool);
        cudaGetSymbolAddress(&p_gcnt, g_gcnt);
        cudaStreamCreateWithFlags(&s2, cudaStreamNonBlocking);
        cudaEventCreateWithFlags(&ev_begin, cudaEventDisableTiming);
        for (int b = 0; b < NB; b++) {
            cudaEventCreateWithFlags(&evq[b], cudaEventDisableTiming);
            cudaEventCreateWithFlags(&evm[b], cudaEventDisableTiming);
        }
        init_done = 1;
    }

    cudaMemsetAsync(p_agg,  0, (size_t)NN * HH * 4, 0);
    cudaMemsetAsync(p_cnt,  0, (size_t)NN * 4, 0);
    cudaMemsetAsync(p_deg,  0, (size_t)NN * 4, 0);
    cudaMemsetAsync(p_pool, 0, (size_t)NGRP * HH * 4, 0);
    cudaMemsetAsync(p_gcnt, 0, (size_t)NGRP * 4, 0);

    k_hist<<<(EE + 255) / 256, 256>>>(ei);
    k_scan<<<1, 1024>>>();
    k_scatter<<<(EE + 255) / 256, 256>>>(ei);

    cudaEventRecord(ev_begin, 0);
    cudaStreamWaitEvent(s2, ev_begin, 0);

    dim3 qg((NPB + 31) / 32, 32);
    for (int b = 0; b < NB; b++) {
        int n0 = b * NPB;
        int which = b & 1;
        if (b >= 2) cudaStreamWaitEvent(s2, evm[b - 2], 0);
        k_Q<<<qg, 256, 0, s2>>>(x, enw2, n0, which);
        cudaEventRecord(evq[b], s2);
        cudaStreamWaitEvent(0, evq[b], 0);
        k_msg<<<NPB, 256>>>(x, ea, ei, enw1, enb1, enb2, n0, which);
        cudaEventRecord(evm[b], 0);
    }

    k_conv<<<(NN * HH + 255) / 256, 256>>>(x, rootw, convb);

    k_redpart<<<NPART, 256>>>(0);
    k_redfin<<<1, NPART>>>(0);

    k_gatprep<<<NN, 64>>>(gatw, attS, attD, n1w, n1b);
    k_gatfused<<<NN, 64>>>(ei, gatb);

    k_redpart<<<NPART, 256>>>(1);
    k_redfin<<<1, NPART>>>(1);

    k_pool<<<(NN * HH + 255) / 256, 256>>>(batch, n2w, n2b);
    k_head<<<NGRP, 64>>>(linw, linb, out);
}

// round 15
// speedup vs baseline: 1.0833x; 1.0833x over previous
#include <cuda_runtime.h>
#include <cuda_bf16.h>
#include <cuda_fp16.h>
#include <cstdint>
#include <math.h>

#define NN   50000
#define EE   300000
#define FIN  16
#define FE   8
#define HH   64
#define HEADS 4
#define NGRP 64
#define KK   1024
#define E2   (EE + NN)
#define NPART 512
#define CHUNKS 16
#define CK   64               // k per chunk
#define NPB  6250             // nodes per Q batch
#define NB   8                // batches

// ---------------- scratch ----------------
// Q ping-pong: [NPB][k/2][hp][2] fp16-pair interleave, 819 MB each
static __device__ __half g_QA[(size_t)NPB * KK * HH];
static __device__ __half g_QB[(size_t)NPB * KK * HH];

static __device__ int   g_cnt[NN];
static __device__ int   g_ptr[NN + 1];
static __device__ int   g_cursor[NN];
static __device__ int   g_eperm[EE];
static __device__ int   g_deg[NN];
static __device__ int   g_ptr2[NN + 1];     // dst CSR
static __device__ int   g_cursor2[NN];
static __device__ int   g_eperm2[EE];
static __device__ float g_agg[NN * HH];
static __device__ float g_h[NN * HH];
static __device__ float g_xh[NN * HH];
static __device__ float g_asrc[NN * HEADS];
static __device__ float g_adst[NN * HEADS];
static __device__ float g_h2[NN * HH];
static __device__ float g_pool[NGRP * HH];
static __device__ int   g_gcnt[NGRP];
static __device__ float g_psum[NPART];
static __device__ float g_psumsq[NPART];
static __device__ float g_stats[4];

__device__ __forceinline__ void cp16(uint32_t dst_s, const void* src_g) {
    asm volatile("cp.async.cg.shared.global [%0], [%1], 16;\n"
                 :: "r"(dst_s), "l"(src_g));
}

// ---------------- CSR by src AND dst ----------------
__global__ void k_hist(const int* __restrict__ ei) {
    int e = blockIdx.x * blockDim.x + threadIdx.x;
    if (e >= EE) return;
    atomicAdd(&g_cnt[ei[e]], 1);
    atomicAdd(&g_deg[ei[EE + e]], 1);
}

__global__ void k_scan() {
    __shared__ int ss[1024];
    const int CH = (NN + 1023) / 1024;
    int t = threadIdx.x;
    int lo = t * CH;
    int hi = lo + CH; if (hi > NN) hi = NN;
    int s = 0;
    for (int i = lo; i < hi; i++) s += g_cnt[i];
    ss[t] = s;
    __syncthreads();
    for (int off = 1; off < 1024; off <<= 1) {
        int v = (t >= off) ? ss[t - off] : 0;
        __syncthreads();
        ss[t] += v;
        __syncthreads();
    }
    int run = ss[t] - s;
    for (int i = lo; i < hi; i++) {
        g_ptr[i] = run;
        g_cursor[i] = run;
        run += g_cnt[i];
    }
    if (t == 0) g_ptr[NN] = EE;
    __syncthreads();
    s = 0;
    for (int i = lo; i < hi; i++) s += g_deg[i];
    ss[t] = s;
    __syncthreads();
    for (int off = 1; off < 1024; off <<= 1) {
        int v = (t >= off) ? ss[t - off] : 0;
        __syncthreads();
        ss[t] += v;
        __syncthreads();
    }
    run = ss[t] - s;
    for (int i = lo; i < hi; i++) {
        g_ptr2[i] = run;
        g_cursor2[i] = run;
        run += g_deg[i];
    }
    if (t == 0) g_ptr2[NN] = EE;
}

__global__ void k_scatter(const int* __restrict__ ei) {
    int e = blockIdx.x * blockDim.x + threadIdx.x;
    if (e >= EE) return;
    int pos = atomicAdd(&g_cursor[ei[e]], 1);
    g_eperm[pos] = e;
    int pos2 = atomicAdd(&g_cursor2[ei[EE + e]], 1);
    g_eperm2[pos2] = e;
}

// ---- Q[nl][kp][hp][2] = sum_f x[n0+nl,f] * W2[k, f*64+h]  (fp16 batch) ----
// R13 champion version: 2 k-rows per thread sharing x LDS loads.
__global__ void __launch_bounds__(256)
k_Q(const float* __restrict__ x, const float* __restrict__ w2, int n0, int which) {
    __half2* q = (__half2*)(which ? g_QB : g_QA);
    int kl = threadIdx.x >> 5;
    int hp = threadIdx.x & 31;
    int kg  = blockIdx.y * 8 + kl;       // 0..511
    int kg2 = kg + 512;                  // 512..1023
    int nl0 = blockIdx.x * 32;

    __shared__ float2 xs2[32 * 16];
    for (int i = threadIdx.x; i < 512; i += 256) {
        int nl = i >> 4, f = i & 15;
        int n = n0 + nl0 + nl;
        float v = (n < NN) ? x[n * 16 + f] : 0.f;
        xs2[i] = make_float2(v, v);
    }

    unsigned long long wp[16], wq[16];
#pragma unroll
    for (int f = 0; f < 16; f++) {
        wp[f] = *(const unsigned long long*)(w2 + (size_t)kg  * 1024 + f * 64 + hp * 2);
        wq[f] = *(const unsigned long long*)(w2 + (size_t)kg2 * 1024 + f * 64 + hp * 2);
    }
    __syncthreads();

    size_t offA = (size_t)(kg  >> 1) * 64 + (hp << 1) + (kg  & 1);
    size_t offB = (size_t)(kg2 >> 1) * 64 + (hp << 1) + (kg2 & 1);

#pragma unroll 2
    for (int nl = 0; nl < 32; nl++) {
        if (nl0 + nl >= NPB) break;
        unsigned long long accA = 0ULL, accB = 0ULL;
        const unsigned long long* xp = (const unsigned long long*)(xs2 + nl * 16);
#pragma unroll
        for (int f = 0; f < 16; f++) {
            unsigned long long xv = xp[f];
            asm("fma.rn.f32x2 %0, %1, %2, %0;" : "+l"(accA) : "l"(xv), "l"(wp[f]));
            asm("fma.rn.f32x2 %0, %1, %2, %0;" : "+l"(accB) : "l"(xv), "l"(wq[f]));
        }
        float loA, hiA, loB, hiB;
        asm("mov.b64 {%0,%1}, %2;" : "=f"(loA), "=f"(hiA) : "l"(accA));
        asm("mov.b64 {%0,%1}, %2;" : "=f"(loB), "=f"(hiB) : "l"(accB));
        size_t nb = (size_t)(nl0 + nl) * 32768;
        q[nb + offA] = __floats2half2_rn(loA, hiA);
        q[nb + offB] = __floats2half2_rn(loB, hiB);
    }
}

// ---- per-edge message: msg = r_e @ Q_src + x_src@b2' ----
// Triple-buffered qbuf -> ONE barrier per chunk; r-compute with paired k
// (float2 w1/b1 loads). Dot loop identical to R13.
__global__ void k_msg(const float* __restrict__ x, const float* __restrict__ ea,
                      const int* __restrict__ ei, const float* __restrict__ w1,
                      const float* __restrict__ b1, const float* __restrict__ b2,
                      int n0, int which) {
    const __half* qb0 = which ? g_QB : g_QA;
    int nl = blockIdx.x;
    int n = n0 + nl;
    int p0 = g_ptr[n], p1 = g_ptr[n + 1];
    if (p0 == p1) return;

    __shared__ __align__(16) uint2 qbuf[3][(CK / 2) * 32];   // 3 x 8KB
    __shared__ __align__(8) float r_s[8][2][CK];
    __shared__ float bx[64];

    int tid = threadIdx.x;
    int wid = tid >> 5, lane = tid & 31;

    if (tid < 64) {
        float s = 0.f;
        const float* xv = x + n * 16;
#pragma unroll
        for (int f = 0; f < 16; f++) s = fmaf(xv[f], b2[f * 64 + tid], s);
        bx[tid] = s;
    }

    const char* qg = (const char*)qb0 + (size_t)nl * (KK * HH * 2);
    uint32_t sbase = (uint32_t)__cvta_generic_to_shared(&qbuf[0][0]);
    uint32_t soff = tid * 16;

    for (int ebase = p0; ebase < p1; ebase += 16) {
        int t0 = ebase + wid, t1 = ebase + 8 + wid;
        bool e0v = t0 < p1, e1v = t1 < p1;
        int dst0 = 0, dst1 = 0;
        float ev0[8], ev1[8];
        if (e0v) {
            int e = g_eperm[t0];
            dst0 = ei[EE + e];
            const float4* p = (const float4*)(ea + (size_t)e * 8);
            float4 u = p[0], v = p[1];
            ev0[0]=u.x; ev0[1]=u.y; ev0[2]=u.z; ev0[3]=u.w;
            ev0[4]=v.x; ev0[5]=v.y; ev0[6]=v.z; ev0[7]=v.w;
        }
        if (e1v) {
            int e = g_eperm[t1];
            dst1 = ei[EE + e];
            const float4* p = (const float4*)(ea + (size_t)e * 8);
            float4 u = p[0], v = p[1];
            ev1[0]=u.x; ev1[1]=u.y; ev1[2]=u.z; ev1[3]=u.w;
            ev1[4]=v.x; ev1[5]=v.y; ev1[6]=v.z; ev1[7]=v.w;
        }
        float a00 = 0.f, a01 = 0.f, a10 = 0.f, a11 = 0.f;

        // prologue: prefetch chunks 0 and 1 (separate commit groups)
        {
            uint32_t d = sbase + soff;
            const char* s = qg + soff;
            cp16(d, s); cp16(d + 4096, s + 4096);
            asm volatile("cp.async.commit_group;");
            d = sbase + 8192 + soff;
            s = qg + 8192 + soff;
            cp16(d, s); cp16(d + 4096, s + 4096);
            asm volatile("cp.async.commit_group;");
        }

        for (int c = 0; c < CHUNKS; c++) {
            // wait for chunk c (at most one newer group may stay pending)
            if (c + 1 < CHUNKS) {
                asm volatile("cp.async.wait_group 1;");
            } else {
                asm volatile("cp.async.wait_group 0;");
            }
            __syncthreads();   // single barrier per chunk (triple buffer)

            // prefetch chunk c+2 into buffer (c+2)%3
            if (c + 2 < CHUNKS) {
                uint32_t d = sbase + ((c + 2) % 3) * 8192 + soff;
                const char* s = qg + (c + 2) * 8192 + soff;
                cp16(d, s); cp16(d + 4096, s + 4096);
                asm volatile("cp.async.commit_group;");
            }

            // r for this chunk: lane handles k-pair (c*64+2*lane, +1)
            int k0 = c * 64 + 2 * lane;
            if (e0v) {
                float2 bb = *(const float2*)(b1 + k0);
                float a0 = bb.x, a1 = bb.y;
#pragma unroll
                for (int f = 0; f < 8; f++) {
                    float2 w = *(const float2*)(w1 + f * 1024 + k0);
                    float e = ev0[f];
                    a0 = fmaf(e, w.x, a0);
                    a1 = fmaf(e, w.y, a1);
                }
                *(float2*)&r_s[wid][0][2 * lane] =
                    make_float2(fmaxf(a0, 0.f), fmaxf(a1, 0.f));
            }
            if (e1v) {
                float2 bb = *(const float2*)(b1 + k0);
                float a0 = bb.x, a1 = bb.y;
#pragma unroll
                for (int f = 0; f < 8; f++) {
                    float2 w = *(const float2*)(w1 + f * 1024 + k0);
                    float e = ev1[f];
                    a0 = fmaf(e, w.x, a0);
                    a1 = fmaf(e, w.y, a1);
                }
                *(float2*)&r_s[wid][1][2 * lane] =
                    make_float2(fmaxf(a0, 0.f), fmaxf(a1, 0.f));
            }
            __syncwarp();

            const uint2* qc = qbuf[c % 3];
            const float2* rr0 = (const float2*)r_s[wid][0];
            const float2* rr1 = (const float2*)r_s[wid][1];
            if (e0v) {
#pragma unroll 8
                for (int kp = 0; kp < CK / 2; kp++) {
                    uint2 v = qc[kp * 32 + lane];
                    float2 qa = __half22float2(*(const __half2*)&v.x);
                    float2 qb = __half22float2(*(const __half2*)&v.y);
                    float2 r0 = rr0[kp];
                    a00 = fmaf(r0.x, qa.x, a00);
                    a01 = fmaf(r0.x, qa.y, a01);
                    a00 = fmaf(r0.y, qb.x, a00);
                    a01 = fmaf(r0.y, qb.y, a01);
                    if (e1v) {
                        float2 r1 = rr1[kp];
                        a10 = fmaf(r1.x, qa.x, a10);
                        a11 = fmaf(r1.x, qa.y, a11);
                        a10 = fmaf(r1.y, qb.x, a10);
                        a11 = fmaf(r1.y, qb.y, a11);
                    }
                }
            }
        }
        __syncthreads();  // protect qbuf before next sweep's prologue

        int h0 = lane * 2;
        if (e0v) {
            atomicAdd(&g_agg[(size_t)dst0 * 64 + h0],     a00 + bx[h0]);
            atomicAdd(&g_agg[(size_t)dst0 * 64 + h0 + 1], a01 + bx[h0 + 1]);
        }
        if (e1v) {
            atomicAdd(&g_agg[(size_t)dst1 * 64 + h0],     a10 + bx[h0]);
            atomicAdd(&g_agg[(size_t)dst1 * 64 + h0 + 1], a11 + bx[h0 + 1]);
        }
    }
}

// ---------------- NNConv epilogue ----------------
__global__ void k_conv(const float* __restrict__ x, const float* __restrict__ rw,
                       const float* __restrict__ cb) {
    int i = blockIdx.x * blockDim.x + threadIdx.x;
    if (i >= NN * HH) return;
    int n = i >> 6, j = i & 63;
    float d = fmaxf((float)g_deg[n], 1.f);
    float v = cb[j] + g_agg[i] / d;
    const float* xv = x + n * 16;
#pragma unroll
    for (int f = 0; f < 16; f++) v = fmaf(xv[f], rw[f * 64 + j], v);
    g_h[i] = fmaxf(v, 0.f);
}

// ---------------- graph layernorm reductions ----------------
__global__ void k_redpart(int which) {
    const float* src = which ? g_h2 : g_h;
    float s = 0.f, q = 0.f;
    for (int i = blockIdx.x * blockDim.x + threadIdx.x; i < NN * HH;
         i += NPART * 256) {
        float v = src[i];
        s += v; q = fmaf(v, v, q);
    }
    __shared__ float bs[256], bq[256];
    bs[threadIdx.x] = s; bq[threadIdx.x] = q;
    __syncthreads();
    for (int off = 128; off; off >>= 1) {
        if (threadIdx.x < off) {
            bs[threadIdx.x] += bs[threadIdx.x + off];
            bq[threadIdx.x] += bq[threadIdx.x + off];
        }
        __syncthreads();
    }
    if (threadIdx.x == 0) { g_psum[blockIdx.x] = bs[0]; g_psumsq[blockIdx.x] = bq[0]; }
}

__global__ void k_redfin(int which) {
    __shared__ double ds[NPART], dq[NPART];
    int t = threadIdx.x;
    ds[t] = (double)g_psum[t];
    dq[t] = (double)g_psumsq[t];
    __syncthreads();
    for (int off = NPART / 2; off; off >>= 1) {
        if (t < off) { ds[t] += ds[t + off]; dq[t] += dq[t + off]; }
        __syncthreads();
    }
    if (t == 0) {
        double M = (double)NN * HH;
        double mu = ds[0] / M;
        double var = dq[0] / M - mu * mu;
        if (var < 0.0) var = 0.0;
        float inv = 1.f / ((float)sqrt(var) + 1e-5f);
        g_stats[2 * which]     = (float)mu;
        g_stats[2 * which + 1] = inv;
    }
}

// ---------------- GAT ----------------
__global__ void k_gatprep(const float* __restrict__ gw, const float* __restrict__ asv,
                          const float* __restrict__ adv, const float* __restrict__ n1w,
                          const float* __restrict__ n1b) {
    int n = blockIdx.x, t = threadIdx.x;
    __shared__ float hs[64];
    float mu = g_stats[0], inv = g_stats[1];
    hs[t] = (g_h[(size_t)n * 64 + t] - mu) * inv * n1w[t] + n1b[t];
    __syncthreads();
    float v = 0.f;
#pragma unroll
    for (int i = 0; i < 64; i++) v = fmaf(hs[i], gw[i * 64 + t], v);
    g_xh[(size_t)n * 64 + t] = v;
    int hd = t >> 4, dd = t & 15;
    float ps = v * asv[t];
    float pd = v * adv[t];
#pragma unroll
    for (int off = 8; off; off >>= 1) {
        ps += __shfl_down_sync(0xffffffffu, ps, off, 16);
        pd += __shfl_down_sync(0xffffffffu, pd, off, 16);
    }
    if (dd == 0) {
        g_asrc[n * 4 + hd] = ps;
        g_adst[n * 4 + hd] = pd;
    }
}

__global__ void k_gatfused(const int* __restrict__ ei, const float* __restrict__ gb) {
    int n = blockIdx.x, t = threadIdx.x;
    int hd = t >> 4;
    int p0 = g_ptr2[n], p1 = g_ptr2[n + 1];
    float adst_n = g_adst[n * 4 + hd];

    float a_self = g_asrc[n * 4 + hd] + adst_n;
    a_self = (a_self > 0.f) ? a_self : 0.2f * a_self;
    float amax = a_self;
    for (int p = p0; p < p1; p++) {
        int s = ei[g_eperm2[p]];
        float a = g_asrc[s * 4 + hd] + adst_n;
        a = (a > 0.f) ? a : 0.2f * a;
        amax = fmaxf(amax, a);
    }
    float w = expf(a_self - amax);
    float sum = w;
    float acc = w * g_xh[(size_t)n * 64 + t];
    for (int p = p0; p < p1; p++) {
        int s = ei[g_eperm2[p]];
        float a = g_asrc[s * 4 + hd] + adst_n;
        a = (a > 0.f) ? a : 0.2f * a;
        float ww = expf(a - amax);
        sum += ww;
        acc = fmaf(ww, g_xh[(size_t)s * 64 + t], acc);
    }
    g_h2[(size_t)n * 64 + t] = fmaxf(acc / (sum + 1e-16f) + gb[t], 0.f);
}

__global__ void k_pool(const int* __restrict__ batch, const float* __restrict__ n2w,
                       const float* __restrict__ n2b) {
    int i = blockIdx.x * blockDim.x + threadIdx.x;
    if (i >= NN * HH) return;
    int n = i >> 6, j = i & 63;
    float v = (g_h2[i] - g_stats[2]) * g_stats[3] * n2w[j] + n2b[j];
    int g = batch[n];
    atomicAdd(&g_pool[g * 64 + j], v);
    if (j == 0) atomicAdd(&g_gcnt[g], 1);
}

__global__ void k_head(const float* __restrict__ lw, const float* __restrict__ lb,
                       float* __restrict__ out) {
    int g = blockIdx.x, t = threadIdx.x;
    float c = fmaxf((float)g_gcnt[g], 1.f);
    float v = (g_pool[g * 64 + t] / c) * lw[t];
    __shared__ float sm[64];
    sm[t] = v;
    __syncthreads();
    for (int off = 32; off; off >>= 1) {
        if (t < off) sm[t] += sm[t + off];
        __syncthreads();
    }
    if (t == 0) out[g] = sm[0] + lb[0];
}

// ---------------- launch ----------------
extern "C" void kernel_launch(void* const* d_in, const int* in_sizes, int n_in,
                              void* d_out, int out_size) {
    const float* x    = (const float*)d_in[0];
    const int*   ei   = (const int*)d_in[1];
    const float* ea   = (const float*)d_in[2];
    const int*   batch= (const int*)d_in[3];
    const float* enw1 = (const float*)d_in[4];
    const float* enb1 = (const float*)d_in[5];
    const float* enw2 = (const float*)d_in[6];
    const float* enb2 = (const float*)d_in[7];
    const float* rootw= (const float*)d_in[8];
    const float* convb= (const float*)d_in[9];
    const float* n1w  = (const float*)d_in[10];
    const float* n1b  = (const float*)d_in[11];
    const float* gatw = (const float*)d_in[12];
    const float* attS = (const float*)d_in[13];
    const float* attD = (const float*)d_in[14];
    const float* gatb = (const float*)d_in[15];
    const float* n2w  = (const float*)d_in[16];
    const float* n2b  = (const float*)d_in[17];
    const float* linw = (const float*)d_in[18];
    const float* linb = (const float*)d_in[19];
    float* out = (float*)d_out;

    static void *p_agg = 0, *p_cnt = 0, *p_deg = 0, *p_pool = 0, *p_gcnt = 0;
    static cudaStream_t s2;
    static cudaEvent_t ev_begin, evq[NB], evm[NB];
    static int init_done = 0;
    if (!init_done) {
        cudaGetSymbolAddress(&p_agg,  g_agg);
        cudaGetSymbolAddress(&p_cnt,  g_cnt);
        cudaGetSymbolAddress(&p_deg,  g_deg);
        cudaGetSymbolAddress(&p_pool, g_pool);
        cudaGetSymbolAddress(&p_gcnt, g_gcnt);
        cudaStreamCreateWithFlags(&s2, cudaStreamNonBlocking);
        cudaEventCreateWithFlags(&ev_begin, cudaEventDisableTiming);
        for (int b = 0; b < NB; b++) {
            cudaEventCreateWithFlags(&evq[b], cudaEventDisableTiming);
            cudaEventCreateWithFlags(&evm[b], cudaEventDisableTiming);
        }
        init_done = 1;
    }

    cudaMemsetAsync(p_agg,  0, (size_t)NN * HH * 4, 0);
    cudaMemsetAsync(p_cnt,  0, (size_t)NN * 4, 0);
    cudaMemsetAsync(p_deg,  0, (size_t)NN * 4, 0);
    cudaMemsetAsync(p_pool, 0, (size_t)NGRP * HH * 4, 0);
    cudaMemsetAsync(p_gcnt, 0, (size_t)NGRP * 4, 0);

    k_hist<<<(EE + 255) / 256, 256>>>(ei);
    k_scan<<<1, 1024>>>();
    k_scatter<<<(EE + 255) / 256, 256>>>(ei);

    cudaEventRecord(ev_begin, 0);
    cudaStreamWaitEvent(s2, ev_begin, 0);

    dim3 qg((NPB + 31) / 32, 64);
    for (int b = 0; b < NB; b++) {
        int n0 = b * NPB;
        int which = b & 1;
        if (b >= 2) cudaStreamWaitEvent(s2, evm[b - 2], 0);
        k_Q<<<qg, 256, 0, s2>>>(x, enw2, n0, which);
        cudaEventRecord(evq[b], s2);
        cudaStreamWaitEvent(0, evq[b], 0);
        k_msg<<<NPB, 256>>>(x, ea, ei, enw1, enb1, enb2, n0, which);
        cudaEventRecord(evm[b], 0);
    }

    k_conv<<<(NN * HH + 255) / 256, 256>>>(x, rootw, convb);

    k_redpart<<<NPART, 256>>>(0);
    k_redfin<<<1, NPART>>>(0);

    k_gatprep<<<NN, 64>>>(gatw, attS, attD, n1w, n1b);
    k_gatfused<<<NN, 64>>>(ei, gatb);

    k_redpart<<<NPART, 256>>>(1);
    k_redfin<<<1, NPART>>>(1);

    k_pool<<<(NN * HH + 255) / 256, 256>>>(batch, n2w, n2b);
    k_head<<<NGRP, 64>>>(linw, linb, out);
}

// round 16
// speedup vs baseline: 1.1258x; 1.0392x over previous
#include <cuda_runtime.h>
#include <cuda_bf16.h>
#include <cuda_fp16.h>
#include <cstdint>
#include <math.h>

#define NN   50000
#define EE   300000
#define FIN  16
#define FE   8
#define HH   64
#define HEADS 4
#define NGRP 64
#define KK   1024
#define E2   (EE + NN)
#define NPART 512
#define CHUNKS 16
#define CK   64               // k per chunk
#define NPB  6250             // nodes per Q batch
#define NB   8                // batches

// ---------------- scratch ----------------
// Q ping-pong: [NPB][k/2][hp][2] fp16-pair interleave, 819 MB each
static __device__ __half g_QA[(size_t)NPB * KK * HH];
static __device__ __half g_QB[(size_t)NPB * KK * HH];

static __device__ int   g_cnt[NN];
static __device__ int   g_ptr[NN + 1];
static __device__ int   g_cursor[NN];
static __device__ int   g_eperm[EE];
static __device__ int   g_deg[NN];
static __device__ int   g_ptr2[NN + 1];     // dst CSR
static __device__ int   g_cursor2[NN];
static __device__ int   g_eperm2[EE];
static __device__ float g_agg[NN * HH];
static __device__ float g_h[NN * HH];
static __device__ float g_xh[NN * HH];
static __device__ float g_asrc[NN * HEADS];
static __device__ float g_adst[NN * HEADS];
static __device__ float g_h2[NN * HH];
static __device__ float g_pool[NGRP * HH];
static __device__ int   g_gcnt[NGRP];
static __device__ float g_psum[NPART];
static __device__ float g_psumsq[NPART];
static __device__ float g_stats[4];

__device__ __forceinline__ void cp16(uint32_t dst_s, const void* src_g) {
    asm volatile("cp.async.cg.shared.global [%0], [%1], 16;\n"
                 :: "r"(dst_s), "l"(src_g));
}

// ---------------- CSR by src AND dst ----------------
__global__ void k_hist(const int* __restrict__ ei) {
    int e = blockIdx.x * blockDim.x + threadIdx.x;
    if (e >= EE) return;
    atomicAdd(&g_cnt[ei[e]], 1);
    atomicAdd(&g_deg[ei[EE + e]], 1);
}

__global__ void k_scan() {
    __shared__ int ss[1024];
    const int CH = (NN + 1023) / 1024;
    int t = threadIdx.x;
    int lo = t * CH;
    int hi = lo + CH; if (hi > NN) hi = NN;
    int s = 0;
    for (int i = lo; i < hi; i++) s += g_cnt[i];
    ss[t] = s;
    __syncthreads();
    for (int off = 1; off < 1024; off <<= 1) {
        int v = (t >= off) ? ss[t - off] : 0;
        __syncthreads();
        ss[t] += v;
        __syncthreads();
    }
    int run = ss[t] - s;
    for (int i = lo; i < hi; i++) {
        g_ptr[i] = run;
        g_cursor[i] = run;
        run += g_cnt[i];
    }
    if (t == 0) g_ptr[NN] = EE;
    __syncthreads();
    s = 0;
    for (int i = lo; i < hi; i++) s += g_deg[i];
    ss[t] = s;
    __syncthreads();
    for (int off = 1; off < 1024; off <<= 1) {
        int v = (t >= off) ? ss[t - off] : 0;
        __syncthreads();
        ss[t] += v;
        __syncthreads();
    }
    run = ss[t] - s;
    for (int i = lo; i < hi; i++) {
        g_ptr2[i] = run;
        g_cursor2[i] = run;
        run += g_deg[i];
    }
    if (t == 0) g_ptr2[NN] = EE;
}

__global__ void k_scatter(const int* __restrict__ ei) {
    int e = blockIdx.x * blockDim.x + threadIdx.x;
    if (e >= EE) return;
    int pos = atomicAdd(&g_cursor[ei[e]], 1);
    g_eperm[pos] = e;
    int pos2 = atomicAdd(&g_cursor2[ei[EE + e]], 1);
    g_eperm2[pos2] = e;
}

// ---- Q[nl][kp][hp][2] = sum_f x[n0+nl,f] * W2[k, f*64+h]  (fp16 batch) ----
// Each thread owns adjacent k-pair (2kp, 2kp+1) -> single dense STG.64.
__global__ void __launch_bounds__(256)
k_Q(const float* __restrict__ x, const float* __restrict__ w2, int n0, int which) {
    __half2* q = (__half2*)(which ? g_QB : g_QA);
    int kl = threadIdx.x >> 5;
    int hp = threadIdx.x & 31;
    int kp = blockIdx.y * 8 + kl;        // pair index 0..511
    int k0 = 2 * kp, k1 = 2 * kp + 1;
    int nl0 = blockIdx.x * 32;

    __shared__ float2 xs2[32 * 16];
    for (int i = threadIdx.x; i < 512; i += 256) {
        int nl = i >> 4, f = i & 15;
        int n = n0 + nl0 + nl;
        float v = (n < NN) ? x[n * 16 + f] : 0.f;
        xs2[i] = make_float2(v, v);
    }

    unsigned long long wp[16], wq[16];
#pragma unroll
    for (int f = 0; f < 16; f++) {
        wp[f] = *(const unsigned long long*)(w2 + (size_t)k0 * 1024 + f * 64 + hp * 2);
        wq[f] = *(const unsigned long long*)(w2 + (size_t)k1 * 1024 + f * 64 + hp * 2);
    }
    __syncthreads();

    // pair-interleave layout: element (k, hp) at kp*64 + hp*2 + (k&1)
    size_t off = (size_t)kp * 64 + (hp << 1);

#pragma unroll 2
    for (int nl = 0; nl < 32; nl++) {
        if (nl0 + nl >= NPB) break;
        unsigned long long accA = 0ULL, accB = 0ULL;
        const unsigned long long* xp = (const unsigned long long*)(xs2 + nl * 16);
#pragma unroll
        for (int f = 0; f < 16; f++) {
            unsigned long long xv = xp[f];
            asm("fma.rn.f32x2 %0, %1, %2, %0;" : "+l"(accA) : "l"(xv), "l"(wp[f]));
            asm("fma.rn.f32x2 %0, %1, %2, %0;" : "+l"(accB) : "l"(xv), "l"(wq[f]));
        }
        float loA, hiA, loB, hiB;
        asm("mov.b64 {%0,%1}, %2;" : "=f"(loA), "=f"(hiA) : "l"(accA));
        asm("mov.b64 {%0,%1}, %2;" : "=f"(loB), "=f"(hiB) : "l"(accB));
        __half2 hA = __floats2half2_rn(loA, hiA);   // k even
        __half2 hB = __floats2half2_rn(loB, hiB);   // k odd
        uint2 st;
        st.x = *(unsigned int*)&hA;
        st.y = *(unsigned int*)&hB;
        *(uint2*)(q + (size_t)(nl0 + nl) * 32768 + off) = st;
    }
}

// ---- per-edge message: msg = r_e @ Q_src + x_src@b2' ----
// Triple-buffered qbuf -> ONE barrier per chunk; paired-k r compute.
__global__ void k_msg(const float* __restrict__ x, const float* __restrict__ ea,
                      const int* __restrict__ ei, const float* __restrict__ w1,
                      const float* __restrict__ b1, const float* __restrict__ b2,
                      int n0, int which) {
    const __half* qb0 = which ? g_QB : g_QA;
    int nl = blockIdx.x;
    int n = n0 + nl;
    int p0 = g_ptr[n], p1 = g_ptr[n + 1];
    if (p0 == p1) return;

    __shared__ __align__(16) uint2 qbuf[3][(CK / 2) * 32];   // 3 x 8KB
    __shared__ __align__(8) float r_s[8][2][CK];
    __shared__ float bx[64];

    int tid = threadIdx.x;
    int wid = tid >> 5, lane = tid & 31;

    if (tid < 64) {
        float s = 0.f;
        const float* xv = x + n * 16;
#pragma unroll
        for (int f = 0; f < 16; f++) s = fmaf(xv[f], b2[f * 64 + tid], s);
        bx[tid] = s;
    }

    const char* qg = (const char*)qb0 + (size_t)nl * (KK * HH * 2);
    uint32_t sbase = (uint32_t)__cvta_generic_to_shared(&qbuf[0][0]);
    uint32_t soff = tid * 16;

    for (int ebase = p0; ebase < p1; ebase += 16) {
        int t0 = ebase + wid, t1 = ebase + 8 + wid;
        bool e0v = t0 < p1, e1v = t1 < p1;
        int dst0 = 0, dst1 = 0;
        float ev0[8], ev1[8];
        if (e0v) {
            int e = g_eperm[t0];
            dst0 = ei[EE + e];
            const float4* p = (const float4*)(ea + (size_t)e * 8);
            float4 u = p[0], v = p[1];
            ev0[0]=u.x; ev0[1]=u.y; ev0[2]=u.z; ev0[3]=u.w;
            ev0[4]=v.x; ev0[5]=v.y; ev0[6]=v.z; ev0[7]=v.w;
        }
        if (e1v) {
            int e = g_eperm[t1];
            dst1 = ei[EE + e];
            const float4* p = (const float4*)(ea + (size_t)e * 8);
            float4 u = p[0], v = p[1];
            ev1[0]=u.x; ev1[1]=u.y; ev1[2]=u.z; ev1[3]=u.w;
            ev1[4]=v.x; ev1[5]=v.y; ev1[6]=v.z; ev1[7]=v.w;
        }
        float a00 = 0.f, a01 = 0.f, a10 = 0.f, a11 = 0.f;

        // prologue: prefetch chunks 0 and 1 (separate commit groups)
        {
            uint32_t d = sbase + soff;
            const char* s = qg + soff;
            cp16(d, s); cp16(d + 4096, s + 4096);
            asm volatile("cp.async.commit_group;");
            d = sbase + 8192 + soff;
            s = qg + 8192 + soff;
            cp16(d, s); cp16(d + 4096, s + 4096);
            asm volatile("cp.async.commit_group;");
        }

        for (int c = 0; c < CHUNKS; c++) {
            if (c + 1 < CHUNKS) {
                asm volatile("cp.async.wait_group 1;");
            } else {
                asm volatile("cp.async.wait_group 0;");
            }
            __syncthreads();   // single barrier per chunk (triple buffer)

            if (c + 2 < CHUNKS) {
                uint32_t d = sbase + ((c + 2) % 3) * 8192 + soff;
                const char* s = qg + (c + 2) * 8192 + soff;
                cp16(d, s); cp16(d + 4096, s + 4096);
                asm volatile("cp.async.commit_group;");
            }

            int k0 = c * 64 + 2 * lane;
            if (e0v) {
                float2 bb = *(const float2*)(b1 + k0);
                float a0 = bb.x, a1 = bb.y;
#pragma unroll
                for (int f = 0; f < 8; f++) {
                    float2 w = *(const float2*)(w1 + f * 1024 + k0);
                    float e = ev0[f];
                    a0 = fmaf(e, w.x, a0);
                    a1 = fmaf(e, w.y, a1);
                }
                *(float2*)&r_s[wid][0][2 * lane] =
                    make_float2(fmaxf(a0, 0.f), fmaxf(a1, 0.f));
            }
            if (e1v) {
                float2 bb = *(const float2*)(b1 + k0);
                float a0 = bb.x, a1 = bb.y;
#pragma unroll
                for (int f = 0; f < 8; f++) {
                    float2 w = *(const float2*)(w1 + f * 1024 + k0);
                    float e = ev1[f];
                    a0 = fmaf(e, w.x, a0);
                    a1 = fmaf(e, w.y, a1);
                }
                *(float2*)&r_s[wid][1][2 * lane] =
                    make_float2(fmaxf(a0, 0.f), fmaxf(a1, 0.f));
            }
            __syncwarp();

            const uint2* qc = qbuf[c % 3];
            const float2* rr0 = (const float2*)r_s[wid][0];
            const float2* rr1 = (const float2*)r_s[wid][1];
            if (e0v) {
#pragma unroll 8
                for (int kp = 0; kp < CK / 2; kp++) {
                    uint2 v = qc[kp * 32 + lane];
                    float2 qa = __half22float2(*(const __half2*)&v.x);
                    float2 qb = __half22float2(*(const __half2*)&v.y);
                    float2 r0 = rr0[kp];
                    a00 = fmaf(r0.x, qa.x, a00);
                    a01 = fmaf(r0.x, qa.y, a01);
                    a00 = fmaf(r0.y, qb.x, a00);
                    a01 = fmaf(r0.y, qb.y, a01);
                    if (e1v) {
                        float2 r1 = rr1[kp];
                        a10 = fmaf(r1.x, qa.x, a10);
                        a11 = fmaf(r1.x, qa.y, a11);
                        a10 = fmaf(r1.y, qb.x, a10);
                        a11 = fmaf(r1.y, qb.y, a11);
                    }
                }
            }
        }
        __syncthreads();  // protect qbuf before next sweep's prologue

        int h0 = lane * 2;
        if (e0v) {
            atomicAdd(&g_agg[(size_t)dst0 * 64 + h0],     a00 + bx[h0]);
            atomicAdd(&g_agg[(size_t)dst0 * 64 + h0 + 1], a01 + bx[h0 + 1]);
        }
        if (e1v) {
            atomicAdd(&g_agg[(size_t)dst1 * 64 + h0],     a10 + bx[h0]);
            atomicAdd(&g_agg[(size_t)dst1 * 64 + h0 + 1], a11 + bx[h0 + 1]);
        }
    }
}

// ---------------- NNConv epilogue ----------------
__global__ void k_conv(const float* __restrict__ x, const float* __restrict__ rw,
                       const float* __restrict__ cb) {
    int i = blockIdx.x * blockDim.x + threadIdx.x;
    if (i >= NN * HH) return;
    int n = i >> 6, j = i & 63;
    float d = fmaxf((float)g_deg[n], 1.f);
    float v = cb[j] + g_agg[i] / d;
    const float* xv = x + n * 16;
#pragma unroll
    for (int f = 0; f < 16; f++) v = fmaf(xv[f], rw[f * 64 + j], v);
    g_h[i] = fmaxf(v, 0.f);
}

// ---------------- graph layernorm reductions ----------------
__global__ void k_redpart(int which) {
    const float* src = which ? g_h2 : g_h;
    float s = 0.f, q = 0.f;
    for (int i = blockIdx.x * blockDim.x + threadIdx.x; i < NN * HH;
         i += NPART * 256) {
        float v = src[i];
        s += v; q = fmaf(v, v, q);
    }
    __shared__ float bs[256], bq[256];
    bs[threadIdx.x] = s; bq[threadIdx.x] = q;
    __syncthreads();
    for (int off = 128; off; off >>= 1) {
        if (threadIdx.x < off) {
            bs[threadIdx.x] += bs[threadIdx.x + off];
            bq[threadIdx.x] += bq[threadIdx.x + off];
        }
        __syncthreads();
    }
    if (threadIdx.x == 0) { g_psum[blockIdx.x] = bs[0]; g_psumsq[blockIdx.x] = bq[0]; }
}

__global__ void k_redfin(int which) {
    __shared__ double ds[NPART], dq[NPART];
    int t = threadIdx.x;
    ds[t] = (double)g_psum[t];
    dq[t] = (double)g_psumsq[t];
    __syncthreads();
    for (int off = NPART / 2; off; off >>= 1) {
        if (t < off) { ds[t] += ds[t + off]; dq[t] += dq[t + off]; }
        __syncthreads();
    }
    if (t == 0) {
        double M = (double)NN * HH;
        double mu = ds[0] / M;
        double var = dq[0] / M - mu * mu;
        if (var < 0.0) var = 0.0;
        float inv = 1.f / ((float)sqrt(var) + 1e-5f);
        g_stats[2 * which]     = (float)mu;
        g_stats[2 * which + 1] = inv;
    }
}

// ---------------- GAT ----------------
__global__ void k_gatprep(const float* __restrict__ gw, const float* __restrict__ asv,
                          const float* __restrict__ adv, const float* __restrict__ n1w,
                          const float* __restrict__ n1b) {
    int n = blockIdx.x, t = threadIdx.x;
    __shared__ float hs[64];
    float mu = g_stats[0], inv = g_stats[1];
    hs[t] = (g_h[(size_t)n * 64 + t] - mu) * inv * n1w[t] + n1b[t];
    __syncthreads();
    float v = 0.f;
#pragma unroll
    for (int i = 0; i < 64; i++) v = fmaf(hs[i], gw[i * 64 + t], v);
    g_xh[(size_t)n * 64 + t] = v;
    int hd = t >> 4, dd = t & 15;
    float ps = v * asv[t];
    float pd = v * adv[t];
#pragma unroll
    for (int off = 8; off; off >>= 1) {
        ps += __shfl_down_sync(0xffffffffu, ps, off, 16);
        pd += __shfl_down_sync(0xffffffffu, pd, off, 16);
    }
    if (dd == 0) {
        g_asrc[n * 4 + hd] = ps;
        g_adst[n * 4 + hd] = pd;
    }
}

__global__ void k_gatfused(const int* __restrict__ ei, const float* __restrict__ gb) {
    int n = blockIdx.x, t = threadIdx.x;
    int hd = t >> 4;
    int p0 = g_ptr2[n], p1 = g_ptr2[n + 1];
    float adst_n = g_adst[n * 4 + hd];

    float a_self = g_asrc[n * 4 + hd] + adst_n;
    a_self = (a_self > 0.f) ? a_self : 0.2f * a_self;
    float amax = a_self;
    for (int p = p0; p < p1; p++) {
        int s = ei[g_eperm2[p]];
        float a = g_asrc[s * 4 + hd] + adst_n;
        a = (a > 0.f) ? a : 0.2f * a;
        amax = fmaxf(amax, a);
    }
    float w = expf(a_self - amax);
    float sum = w;
    float acc = w * g_xh[(size_t)n * 64 + t];
    for (int p = p0; p < p1; p++) {
        int s = ei[g_eperm2[p]];
        float a = g_asrc[s * 4 + hd] + adst_n;
        a = (a > 0.f) ? a : 0.2f * a;
        float ww = expf(a - amax);
        sum += ww;
        acc = fmaf(ww, g_xh[(size_t)s * 64 + t], acc);
    }
    g_h2[(size_t)n * 64 + t] = fmaxf(acc / (sum + 1e-16f) + gb[t], 0.f);
}

__global__ void k_pool(const int* __restrict__ batch, const float* __restrict__ n2w,
                       const float* __restrict__ n2b) {
    int i = blockIdx.x * blockDim.x + threadIdx.x;
    if (i >= NN * HH) return;
    int n = i >> 6, j = i & 63;
    float v = (g_h2[i] - g_stats[2]) * g_stats[3] * n2w[j] + n2b[j];
    int g = batch[n];
    atomicAdd(&g_pool[g * 64 + j], v);
    if (j == 0) atomicAdd(&g_gcnt[g], 1);
}

__global__ void k_head(const float* __restrict__ lw, const float* __restrict__ lb,
                       float* __restrict__ out) {
    int g = blockIdx.x, t = threadIdx.x;
    float c = fmaxf((float)g_gcnt[g], 1.f);
    float v = (g_pool[g * 64 + t] / c) * lw[t];
    __shared__ float sm[64];
    sm[t] = v;
    __syncthreads();
    for (int off = 32; off; off >>= 1) {
        if (t < off) sm[t] += sm[t + off];
        __syncthreads();
    }
    if (t == 0) out[g] = sm[0] + lb[0];
}

// ---------------- launch ----------------
extern "C" void kernel_launch(void* const* d_in, const int* in_sizes, int n_in,
                              void* d_out, int out_size) {
    const float* x    = (const float*)d_in[0];
    const int*   ei   = (const int*)d_in[1];
    const float* ea   = (const float*)d_in[2];
    const int*   batch= (const int*)d_in[3];
    const float* enw1 = (const float*)d_in[4];
    const float* enb1 = (const float*)d_in[5];
    const float* enw2 = (const float*)d_in[6];
    const float* enb2 = (const float*)d_in[7];
    const float* rootw= (const float*)d_in[8];
    const float* convb= (const float*)d_in[9];
    const float* n1w  = (const float*)d_in[10];
    const float* n1b  = (const float*)d_in[11];
    const float* gatw = (const float*)d_in[12];
    const float* attS = (const float*)d_in[13];
    const float* attD = (const float*)d_in[14];
    const float* gatb = (const float*)d_in[15];
    const float* n2w  = (const float*)d_in[16];
    const float* n2b  = (const float*)d_in[17];
    const float* linw = (const float*)d_in[18];
    const float* linb = (const float*)d_in[19];
    float* out = (float*)d_out;

    static void *p_agg = 0, *p_cnt = 0, *p_deg = 0, *p_pool = 0, *p_gcnt = 0;
    static cudaStream_t s2;
    static cudaEvent_t ev_begin, evq[NB], evm[NB];
    static int init_done = 0;
    if (!init_done) {
        cudaGetSymbolAddress(&p_agg,  g_agg);
        cudaGetSymbolAddress(&p_cnt,  g_cnt);
        cudaGetSymbolAddress(&p_deg,  g_deg);
        cudaGetSymbolAddress(&p_pool, g_pool);
        cudaGetSymbolAddress(&p_gcnt, g_gcnt);
        cudaStreamCreateWithFlags(&s2, cudaStreamNonBlocking);
        cudaEventCreateWithFlags(&ev_begin, cudaEventDisableTiming);
        for (int b = 0; b < NB; b++) {
            cudaEventCreateWithFlags(&evq[b], cudaEventDisableTiming);
            cudaEventCreateWithFlags(&evm[b], cudaEventDisableTiming);
        }
        init_done = 1;
    }

    cudaMemsetAsync(p_agg,  0, (size_t)NN * HH * 4, 0);
    cudaMemsetAsync(p_cnt,  0, (size_t)NN * 4, 0);
    cudaMemsetAsync(p_deg,  0, (size_t)NN * 4, 0);
    cudaMemsetAsync(p_pool, 0, (size_t)NGRP * HH * 4, 0);
    cudaMemsetAsync(p_gcnt, 0, (size_t)NGRP * 4, 0);

    k_hist<<<(EE + 255) / 256, 256>>>(ei);
    k_scan<<<1, 1024>>>();
    k_scatter<<<(EE + 255) / 256, 256>>>(ei);

    cudaEventRecord(ev_begin, 0);
    cudaStreamWaitEvent(s2, ev_begin, 0);

    dim3 qg((NPB + 31) / 32, 64);
    for (int b = 0; b < NB; b++) {
        int n0 = b * NPB;
        int which = b & 1;
        if (b >= 2) cudaStreamWaitEvent(s2, evm[b - 2], 0);
        k_Q<<<qg, 256, 0, s2>>>(x, enw2, n0, which);
        cudaEventRecord(evq[b], s2);
        cudaStreamWaitEvent(0, evq[b], 0);
        k_msg<<<NPB, 256>>>(x, ea, ei, enw1, enb1, enb2, n0, which);
        cudaEventRecord(evm[b], 0);
    }

    k_conv<<<(NN * HH + 255) / 256, 256>>>(x, rootw, convb);

    k_redpart<<<NPART, 256>>>(0);
    k_redfin<<<1, NPART>>>(0);

    k_gatprep<<<NN, 64>>>(gatw, attS, attD, n1w, n1b);
    k_gatfused<<<NN, 64>>>(ei, gatb);

    k_redpart<<<NPART, 256>>>(1);
    k_redfin<<<1, NPART>>>(1);

    k_pool<<<(NN * HH + 255) / 256, 256>>>(batch, n2w, n2b);
    k_head<<<NGRP, 64>>>(linw, linb, out);
}

// round 17
// speedup vs baseline: 1.1914x; 1.0583x over previous
#include <cuda_runtime.h>
#include <cuda_bf16.h>
#include <cuda_fp16.h>
#include <cstdint>
#include <math.h>

#define NN   50000
#define EE   300000
#define FIN  16
#define FE   8
#define HH   64
#define HEADS 4
#define NGRP 64
#define KK   1024
#define E2   (EE + NN)
#define NPART 512
#define CHUNKS 16
#define CK   64               // k per chunk
#define NPB  6250             // nodes per Q batch
#define NB   8                // batches

// dynamic smem layout for k_msg (bytes)
#define QROWB   272                      // padded row: 64 half2 + 16B pad
#define QBUFB   (32 * QROWB)             // 8704 per chunk buffer
#define SM_RH   (3 * QBUFB)              // 26112
#define RSTRIDE 514                      // half2 stride per edge row
#define SM_BX   (SM_RH + 16 * RSTRIDE * 4)   // 26112+32896 = 59008
#define SM_TOT  (SM_BX + 256)            // 59264

// ---------------- scratch ----------------
// Q ping-pong: [NPB][kp][h] half2=(k even,k odd), 819 MB each
static __device__ __half g_QA[(size_t)NPB * KK * HH];
static __device__ __half g_QB[(size_t)NPB * KK * HH];

static __device__ int   g_cnt[NN];
static __device__ int   g_ptr[NN + 1];
static __device__ int   g_cursor[NN];
static __device__ int   g_eperm[EE];
static __device__ int   g_deg[NN];
static __device__ int   g_ptr2[NN + 1];     // dst CSR
static __device__ int   g_cursor2[NN];
static __device__ int   g_eperm2[EE];
static __device__ float g_agg[NN * HH];
static __device__ float g_h[NN * HH];
static __device__ float g_xh[NN * HH];
static __device__ float g_asrc[NN * HEADS];
static __device__ float g_adst[NN * HEADS];
static __device__ float g_h2[NN * HH];
static __device__ float g_pool[NGRP * HH];
static __device__ int   g_gcnt[NGRP];
static __device__ float g_psum[NPART];
static __device__ float g_psumsq[NPART];
static __device__ float g_stats[4];

__device__ __forceinline__ void cp16(uint32_t dst_s, const void* src_g) {
    asm volatile("cp.async.cg.shared.global [%0], [%1], 16;\n"
                 :: "r"(dst_s), "l"(src_g));
}

// ---------------- CSR by src AND dst ----------------
__global__ void k_hist(const int* __restrict__ ei) {
    int e = blockIdx.x * blockDim.x + threadIdx.x;
    if (e >= EE) return;
    atomicAdd(&g_cnt[ei[e]], 1);
    atomicAdd(&g_deg[ei[EE + e]], 1);
}

__global__ void k_scan() {
    __shared__ int ss[1024];
    const int CH = (NN + 1023) / 1024;
    int t = threadIdx.x;
    int lo = t * CH;
    int hi = lo + CH; if (hi > NN) hi = NN;
    int s = 0;
    for (int i = lo; i < hi; i++) s += g_cnt[i];
    ss[t] = s;
    __syncthreads();
    for (int off = 1; off < 1024; off <<= 1) {
        int v = (t >= off) ? ss[t - off] : 0;
        __syncthreads();
        ss[t] += v;
        __syncthreads();
    }
    int run = ss[t] - s;
    for (int i = lo; i < hi; i++) {
        g_ptr[i] = run;
        g_cursor[i] = run;
        run += g_cnt[i];
    }
    if (t == 0) g_ptr[NN] = EE;
    __syncthreads();
    s = 0;
    for (int i = lo; i < hi; i++) s += g_deg[i];
    ss[t] = s;
    __syncthreads();
    for (int off = 1; off < 1024; off <<= 1) {
        int v = (t >= off) ? ss[t - off] : 0;
        __syncthreads();
        ss[t] += v;
        __syncthreads();
    }
    run = ss[t] - s;
    for (int i = lo; i < hi; i++) {
        g_ptr2[i] = run;
        g_cursor2[i] = run;
        run += g_deg[i];
    }
    if (t == 0) g_ptr2[NN] = EE;
}

__global__ void k_scatter(const int* __restrict__ ei) {
    int e = blockIdx.x * blockDim.x + threadIdx.x;
    if (e >= EE) return;
    int pos = atomicAdd(&g_cursor[ei[e]], 1);
    g_eperm[pos] = e;
    int pos2 = atomicAdd(&g_cursor2[ei[EE + e]], 1);
    g_eperm2[pos2] = e;
}

// ---- Q2[nl][kp][h] = half2( val(k=2kp,h), val(k=2kp+1,h) )  (fp16 batch) --
// Each thread owns adjacent k-pair -> same dense STG.64 addresses as R16,
// only the half packing changed (k-pair per h instead of h-pair per k).
__global__ void __launch_bounds__(256)
k_Q(const float* __restrict__ x, const float* __restrict__ w2, int n0, int which) {
    __half2* q = (__half2*)(which ? g_QB : g_QA);
    int kl = threadIdx.x >> 5;
    int hp = threadIdx.x & 31;
    int kp = blockIdx.y * 8 + kl;        // pair index 0..511
    int k0 = 2 * kp, k1 = 2 * kp + 1;
    int nl0 = blockIdx.x * 32;

    __shared__ float2 xs2[32 * 16];
    for (int i = threadIdx.x; i < 512; i += 256) {
        int nl = i >> 4, f = i & 15;
        int n = n0 + nl0 + nl;
        float v = (n < NN) ? x[n * 16 + f] : 0.f;
        xs2[i] = make_float2(v, v);
    }

    unsigned long long wp[16], wq[16];
#pragma unroll
    for (int f = 0; f < 16; f++) {
        wp[f] = *(const unsigned long long*)(w2 + (size_t)k0 * 1024 + f * 64 + hp * 2);
        wq[f] = *(const unsigned long long*)(w2 + (size_t)k1 * 1024 + f * 64 + hp * 2);
    }
    __syncthreads();

    size_t off = (size_t)kp * 64 + (hp << 1);   // h = 2hp, 2hp+1

#pragma unroll 2
    for (int nl = 0; nl < 32; nl++) {
        if (nl0 + nl >= NPB) break;
        unsigned long long accA = 0ULL, accB = 0ULL;
        const unsigned long long* xp = (const unsigned long long*)(xs2 + nl * 16);
#pragma unroll
        for (int f = 0; f < 16; f++) {
            unsigned long long xv = xp[f];
            asm("fma.rn.f32x2 %0, %1, %2, %0;" : "+l"(accA) : "l"(xv), "l"(wp[f]));
            asm("fma.rn.f32x2 %0, %1, %2, %0;" : "+l"(accB) : "l"(xv), "l"(wq[f]));
        }
        float loA, hiA, loB, hiB;   // loA=(k0,h0) hiA=(k0,h1) loB=(k1,h0) hiB=(k1,h1)
        asm("mov.b64 {%0,%1}, %2;" : "=f"(loA), "=f"(hiA) : "l"(accA));
        asm("mov.b64 {%0,%1}, %2;" : "=f"(loB), "=f"(hiB) : "l"(accB));
        __half2 h0p = __floats2half2_rn(loA, loB);  // (k0,k1) @ h0
        __half2 h1p = __floats2half2_rn(hiA, hiB);  // (k0,k1) @ h1
        uint2 st;
        st.x = *(unsigned int*)&h0p;
        st.y = *(unsigned int*)&h1p;
        *(uint2*)(q + (size_t)(nl0 + nl) * 32768 + off) = st;
    }
}

// ---- per-edge message via tensor cores: msg = r_e @ Q_src + x_src@b2' ----
// 16 edges per sweep; r precomputed fp16 for whole sweep; each warp owns an
// 8-wide h slice and runs m16n8k16 HMMA over k.
__global__ void k_msg(const float* __restrict__ x, const float* __restrict__ ea,
                      const int* __restrict__ ei, const float* __restrict__ w1,
                      const float* __restrict__ b1, const float* __restrict__ b2,
                      int n0, int which) {
    const __half* qb0 = which ? g_QB : g_QA;
    int nl = blockIdx.x;
    int n = n0 + nl;
    int p0 = g_ptr[n], p1 = g_ptr[n + 1];
    if (p0 == p1) return;

    extern __shared__ char smem[];
    uint32_t* rh = (uint32_t*)(smem + SM_RH);        // [16][RSTRIDE] half2
    float* bx = (float*)(smem + SM_BX);
    __shared__ int dst_s[16];

    int tid = threadIdx.x;
    int wid = tid >> 5, lane = tid & 31;
    int g = lane >> 2, tg = lane & 3;

    if (tid < 64) {
        float s = 0.f;
        const float* xv = x + n * 16;
#pragma unroll
        for (int f = 0; f < 16; f++) s = fmaf(xv[f], b2[f * 64 + tid], s);
        bx[tid] = s;
    }

    const char* qg = (const char*)qb0 + (size_t)nl * (KK * HH * 2);
    uint32_t sbase = (uint32_t)__cvta_generic_to_shared(smem);

    for (int ebase = p0; ebase < p1; ebase += 16) {
        __syncthreads();   // protect rh/dst_s/qbuf from previous sweep readers

        if (tid < 16) {
            int pos = ebase + tid;
            dst_s[tid] = (pos < p1) ? ei[EE + g_eperm[pos]] : 0;
        }

        // ---- r for whole sweep: warp w handles edges 2w, 2w+1 ----
#pragma unroll
        for (int j = 0; j < 2; j++) {
            int el = wid * 2 + j;
            int pos = ebase + el;
            if (pos >= p1) continue;
            int e = g_eperm[pos];
            const float4* p = (const float4*)(ea + (size_t)e * 8);
            float4 u = p[0], v = p[1];
            float ev[8] = {u.x, u.y, u.z, u.w, v.x, v.y, v.z, v.w};
#pragma unroll 4
            for (int c = 0; c < CHUNKS; c++) {
                int k0 = c * 64 + 2 * lane;
                float2 bb = *(const float2*)(b1 + k0);
                float a0 = bb.x, a1 = bb.y;
#pragma unroll
                for (int f = 0; f < 8; f++) {
                    float2 w = *(const float2*)(w1 + f * 1024 + k0);
                    float e2 = ev[f];
                    a0 = fmaf(e2, w.x, a0);
                    a1 = fmaf(e2, w.y, a1);
                }
                __half2 hr = __floats2half2_rn(fmaxf(a0, 0.f), fmaxf(a1, 0.f));
                rh[el * RSTRIDE + c * 32 + lane] = *(uint32_t*)&hr;
            }
        }

        // ---- prefetch chunks 0,1 (padded rows: seg s -> kp=s>>4, col seg s&15)
        {
            int s0 = tid, s1 = tid + 256;
            uint32_t d0 = sbase + (s0 >> 4) * QROWB + (s0 & 15) * 16;
            uint32_t d1 = sbase + (s1 >> 4) * QROWB + (s1 & 15) * 16;
            cp16(d0, qg + s0 * 16);
            cp16(d1, qg + s1 * 16);
            asm volatile("cp.async.commit_group;");
            d0 = sbase + QBUFB + (s0 >> 4) * QROWB + (s0 & 15) * 16;
            d1 = sbase + QBUFB + (s1 >> 4) * QROWB + (s1 & 15) * 16;
            cp16(d0, qg + 8192 + s0 * 16);
            cp16(d1, qg + 8192 + s1 * 16);
            asm volatile("cp.async.commit_group;");
        }

        float c0 = 0.f, c1 = 0.f, c2 = 0.f, c3 = 0.f;
        int hcol = wid * 8 + g;

        for (int c = 0; c < CHUNKS; c++) {
            if (c + 1 < CHUNKS) {
                asm volatile("cp.async.wait_group 1;");
            } else {
                asm volatile("cp.async.wait_group 0;");
            }
            __syncthreads();

            if (c + 2 < CHUNKS) {
                int buf = (c + 2) % 3;
                int s0 = tid, s1 = tid + 256;
                uint32_t d0 = sbase + buf * QBUFB + (s0 >> 4) * QROWB + (s0 & 15) * 16;
                uint32_t d1 = sbase + buf * QBUFB + (s1 >> 4) * QROWB + (s1 & 15) * 16;
                cp16(d0, qg + (c + 2) * 8192 + s0 * 16);
                cp16(d1, qg + (c + 2) * 8192 + s1 * 16);
                asm volatile("cp.async.commit_group;");
            }

            const uint32_t* qc = (const uint32_t*)(smem + (c % 3) * QBUFB);
            int kpb = c * 32;
#pragma unroll
            for (int s = 0; s < 4; s++) {
                uint32_t a0 = rh[g * RSTRIDE + kpb + s * 8 + tg];
                uint32_t a1 = rh[(g + 8) * RSTRIDE + kpb + s * 8 + tg];
                uint32_t a2 = rh[g * RSTRIDE + kpb + s * 8 + tg + 4];
                uint32_t a3 = rh[(g + 8) * RSTRIDE + kpb + s * 8 + tg + 4];
                uint32_t b0 = qc[(s * 8 + tg) * 68 + hcol];
                uint32_t b1v = qc[(s * 8 + tg + 4) * 68 + hcol];
                asm volatile(
                    "mma.sync.aligned.m16n8k16.row.col.f32.f16.f16.f32 "
                    "{%0,%1,%2,%3}, {%4,%5,%6,%7}, {%8,%9}, {%0,%1,%2,%3};"
                    : "+f"(c0), "+f"(c1), "+f"(c2), "+f"(c3)
                    : "r"(a0), "r"(a1), "r"(a2), "r"(a3), "r"(b0), "r"(b1v));
            }
        }

        // ---- emit: D row=edge, col=h; c0/c1 -> edge g, c2/c3 -> edge g+8 ----
        int h0 = wid * 8 + tg * 2;
        if (ebase + g < p1) {
            int d = dst_s[g];
            atomicAdd(&g_agg[(size_t)d * 64 + h0],     c0 + bx[h0]);
            atomicAdd(&g_agg[(size_t)d * 64 + h0 + 1], c1 + bx[h0 + 1]);
        }
        if (ebase + g + 8 < p1) {
            int d = dst_s[g + 8];
            atomicAdd(&g_agg[(size_t)d * 64 + h0],     c2 + bx[h0]);
            atomicAdd(&g_agg[(size_t)d * 64 + h0 + 1], c3 + bx[h0 + 1]);
        }
    }
}

// ---------------- NNConv epilogue ----------------
__global__ void k_conv(const float* __restrict__ x, const float* __restrict__ rw,
                       const float* __restrict__ cb) {
    int i = blockIdx.x * blockDim.x + threadIdx.x;
    if (i >= NN * HH) return;
    int n = i >> 6, j = i & 63;
    float d = fmaxf((float)g_deg[n], 1.f);
    float v = cb[j] + g_agg[i] / d;
    const float* xv = x + n * 16;
#pragma unroll
    for (int f = 0; f < 16; f++) v = fmaf(xv[f], rw[f * 64 + j], v);
    g_h[i] = fmaxf(v, 0.f);
}

// ---------------- graph layernorm reductions ----------------
__global__ void k_redpart(int which) {
    const float* src = which ? g_h2 : g_h;
    float s = 0.f, q = 0.f;
    for (int i = blockIdx.x * blockDim.x + threadIdx.x; i < NN * HH;
         i += NPART * 256) {
        float v = src[i];
        s += v; q = fmaf(v, v, q);
    }
    __shared__ float bs[256], bq[256];
    bs[threadIdx.x] = s; bq[threadIdx.x] = q;
    __syncthreads();
    for (int off = 128; off; off >>= 1) {
        if (threadIdx.x < off) {
            bs[threadIdx.x] += bs[threadIdx.x + off];
            bq[threadIdx.x] += bq[threadIdx.x + off];
        }
        __syncthreads();
    }
    if (threadIdx.x == 0) { g_psum[blockIdx.x] = bs[0]; g_psumsq[blockIdx.x] = bq[0]; }
}

__global__ void k_redfin(int which) {
    __shared__ double ds[NPART], dq[NPART];
    int t = threadIdx.x;
    ds[t] = (double)g_psum[t];
    dq[t] = (double)g_psumsq[t];
    __syncthreads();
    for (int off = NPART / 2; off; off >>= 1) {
        if (t < off) { ds[t] += ds[t + off]; dq[t] += dq[t + off]; }
        __syncthreads();
    }
    if (t == 0) {
        double M = (double)NN * HH;
        double mu = ds[0] / M;
        double var = dq[0] / M - mu * mu;
        if (var < 0.0) var = 0.0;
        float inv = 1.f / ((float)sqrt(var) + 1e-5f);
        g_stats[2 * which]     = (float)mu;
        g_stats[2 * which + 1] = inv;
    }
}

// ---------------- GAT ----------------
__global__ void k_gatprep(const float* __restrict__ gw, const float* __restrict__ asv,
                          const float* __restrict__ adv, const float* __restrict__ n1w,
                          const float* __restrict__ n1b) {
    int n = blockIdx.x, t = threadIdx.x;
    __shared__ float hs[64];
    float mu = g_stats[0], inv = g_stats[1];
    hs[t] = (g_h[(size_t)n * 64 + t] - mu) * inv * n1w[t] + n1b[t];
    __syncthreads();
    float v = 0.f;
#pragma unroll
    for (int i = 0; i < 64; i++) v = fmaf(hs[i], gw[i * 64 + t], v);
    g_xh[(size_t)n * 64 + t] = v;
    int hd = t >> 4, dd = t & 15;
    float ps = v * asv[t];
    float pd = v * adv[t];
#pragma unroll
    for (int off = 8; off; off >>= 1) {
        ps += __shfl_down_sync(0xffffffffu, ps, off, 16);
        pd += __shfl_down_sync(0xffffffffu, pd, off, 16);
    }
    if (dd == 0) {
        g_asrc[n * 4 + hd] = ps;
        g_adst[n * 4 + hd] = pd;
    }
}

__global__ void k_gatfused(const int* __restrict__ ei, const float* __restrict__ gb) {
    int n = blockIdx.x, t = threadIdx.x;
    int hd = t >> 4;
    int p0 = g_ptr2[n], p1 = g_ptr2[n + 1];
    float adst_n = g_adst[n * 4 + hd];

    float a_self = g_asrc[n * 4 + hd] + adst_n;
    a_self = (a_self > 0.f) ? a_self : 0.2f * a_self;
    float amax = a_self;
    for (int p = p0; p < p1; p++) {
        int s = ei[g_eperm2[p]];
        float a = g_asrc[s * 4 + hd] + adst_n;
        a = (a > 0.f) ? a : 0.2f * a;
        amax = fmaxf(amax, a);
    }
    float w = expf(a_self - amax);
    float sum = w;
    float acc = w * g_xh[(size_t)n * 64 + t];
    for (int p = p0; p < p1; p++) {
        int s = ei[g_eperm2[p]];
        float a = g_asrc[s * 4 + hd] + adst_n;
        a = (a > 0.f) ? a : 0.2f * a;
        float ww = expf(a - amax);
        sum += ww;
        acc = fmaf(ww, g_xh[(size_t)s * 64 + t], acc);
    }
    g_h2[(size_t)n * 64 + t] = fmaxf(acc / (sum + 1e-16f) + gb[t], 0.f);
}

__global__ void k_pool(const int* __restrict__ batch, const float* __restrict__ n2w,
                       const float* __restrict__ n2b) {
    int i = blockIdx.x * blockDim.x + threadIdx.x;
    if (i >= NN * HH) return;
    int n = i >> 6, j = i & 63;
    float v = (g_h2[i] - g_stats[2]) * g_stats[3] * n2w[j] + n2b[j];
    int g = batch[n];
    atomicAdd(&g_pool[g * 64 + j], v);
    if (j == 0) atomicAdd(&g_gcnt[g], 1);
}

__global__ void k_head(const float* __restrict__ lw, const float* __restrict__ lb,
                       float* __restrict__ out) {
    int g = blockIdx.x, t = threadIdx.x;
    float c = fmaxf((float)g_gcnt[g], 1.f);
    float v = (g_pool[g * 64 + t] / c) * lw[t];
    __shared__ float sm[64];
    sm[t] = v;
    __syncthreads();
    for (int off = 32; off; off >>= 1) {
        if (t < off) sm[t] += sm[t + off];
        __syncthreads();
    }
    if (t == 0) out[g] = sm[0] + lb[0];
}

// ---------------- launch ----------------
extern "C" void kernel_launch(void* const* d_in, const int* in_sizes, int n_in,
                              void* d_out, int out_size) {
    const float* x    = (const float*)d_in[0];
    const int*   ei   = (const int*)d_in[1];
    const float* ea   = (const float*)d_in[2];
    const int*   batch= (const int*)d_in[3];
    const float* enw1 = (const float*)d_in[4];
    const float* enb1 = (const float*)d_in[5];
    const float* enw2 = (const float*)d_in[6];
    const float* enb2 = (const float*)d_in[7];
    const float* rootw= (const float*)d_in[8];
    const float* convb= (const float*)d_in[9];
    const float* n1w  = (const float*)d_in[10];
    const float* n1b  = (const float*)d_in[11];
    const float* gatw = (const float*)d_in[12];
    const float* attS = (const float*)d_in[13];
    const float* attD = (const float*)d_in[14];
    const float* gatb = (const float*)d_in[15];
    const float* n2w  = (const float*)d_in[16];
    const float* n2b  = (const float*)d_in[17];
    const float* linw = (const float*)d_in[18];
    const float* linb = (const float*)d_in[19];
    float* out = (float*)d_out;

    static void *p_agg = 0, *p_cnt = 0, *p_deg = 0, *p_pool = 0, *p_gcnt = 0;
    static cudaStream_t s2;
    static cudaEvent_t ev_begin, evq[NB], evm[NB];
    static int init_done = 0;
    if (!init_done) {
        cudaGetSymbolAddress(&p_agg,  g_agg);
        cudaGetSymbolAddress(&p_cnt,  g_cnt);
        cudaGetSymbolAddress(&p_deg,  g_deg);
        cudaGetSymbolAddress(&p_pool, g_pool);
        cudaGetSymbolAddress(&p_gcnt, g_gcnt);
        cudaStreamCreateWithFlags(&s2, cudaStreamNonBlocking);
        cudaEventCreateWithFlags(&ev_begin, cudaEventDisableTiming);
        for (int b = 0; b < NB; b++) {
            cudaEventCreateWithFlags(&evq[b], cudaEventDisableTiming);
            cudaEventCreateWithFlags(&evm[b], cudaEventDisableTiming);
        }
        cudaFuncSetAttribute(k_msg, cudaFuncAttributeMaxDynamicSharedMemorySize,
                             SM_TOT);
        init_done = 1;
    }

    cudaMemsetAsync(p_agg,  0, (size_t)NN * HH * 4, 0);
    cudaMemsetAsync(p_cnt,  0, (size_t)NN * 4, 0);
    cudaMemsetAsync(p_deg,  0, (size_t)NN * 4, 0);
    cudaMemsetAsync(p_pool, 0, (size_t)NGRP * HH * 4, 0);
    cudaMemsetAsync(p_gcnt, 0, (size_t)NGRP * 4, 0);

    k_hist<<<(EE + 255) / 256, 256>>>(ei);
    k_scan<<<1, 1024>>>();
    k_scatter<<<(EE + 255) / 256, 256>>>(ei);

    cudaEventRecord(ev_begin, 0);
    cudaStreamWaitEvent(s2, ev_begin, 0);

    dim3 qg((NPB + 31) / 32, 64);
    for (int b = 0; b < NB; b++) {
        int n0 = b * NPB;
        int which = b & 1;
        if (b >= 2) cudaStreamWaitEvent(s2, evm[b - 2], 0);
        k_Q<<<qg, 256, 0, s2>>>(x, enw2, n0, which);
        cudaEventRecord(evq[b], s2);
        cudaStreamWaitEvent(0, evq[b], 0);
        k_msg<<<NPB, 256, SM_TOT>>>(x, ea, ei, enw1, enb1, enb2, n0, which);
        cudaEventRecord(evm[b], 0);
    }

    k_conv<<<(NN * HH + 255) / 256, 256>>>(x, rootw, convb);

    k_redpart<<<NPART, 256>>>(0);
    k_redfin<<<1, NPART>>>(0);

    k_gatprep<<<NN, 64>>>(gatw, attS, attD, n1w, n1b);
    k_gatfused<<<NN, 64>>>(ei, gatb);

    k_redpart<<<NPART, 256>>>(1);
    k_redfin<<<1, NPART>>>(1);

    k_pool<<<(NN * HH + 255) / 256, 256>>>(batch, n2w, n2b);
    k_head<<<NGRP, 64>>>(linw, linb, out);
}